// round 11
// baseline (speedup 1.0000x reference)
#include <cuda_runtime.h>
#include <math.h>

#define BB 8
#define SS 256
#define DD 512
#define NNODE 64
#define VV 32000

typedef unsigned long long u64;

// ---------------- scratch (device globals: allocation-free) ----------------
__device__ float g_xg[BB * SS * DD];          // x @ WgX + bg   (4 MB)
__device__ float g_xu[BB * SS * DD];          // x @ WuX + bu   (4 MB)
__device__ float g_H[2][BB * NNODE * DD];     // node state, double buffered (2 MB)
__device__ float g_cons[BB * SS * DD];        // consensus per (b,t)  (4 MB)
__device__ float g_cln[BB * SS * DD];         // layernormed consensus (4 MB)
__device__ unsigned g_bar[BB];                // per-batch inter-CTA barrier counters

// packed fp32x2 FMA (sm_103a FFMA2) — d.lo += a.lo*b.lo; d.hi += a.hi*b.hi
#define FFMA2(d, a, b) asm("fma.rn.f32x2 %0, %1, %2, %0;" : "+l"(d) : "l"(a), "l"(b))

__device__ __forceinline__ float2 u2f(u64 v) {
    float2 r;
    asm("mov.b64 {%0,%1}, %2;" : "=f"(r.x), "=f"(r.y) : "l"(v));
    return r;
}

// SMEM layout (floats)
#define W_STRIDE 66     // Wsm row: 64 interleaved (g,u) + 2 pad
#define WD_STRIDE 132   // Wdup row: 128 dup floats + 4 pad (528B, 16B-mult)
#define AK_STRIDE 68    // Ak row: 64 nodes + 4 pad (272B, 16B-mult)
#define OFF_WSM  0
#define OFF_WDUP (512 * W_STRIDE)                    // 33792
#define OFF_AK   (OFF_WDUP + 2 * 32 * WD_STRIDE)     // +8448
#define OFF_CP   (OFF_AK + 2 * 32 * AK_STRIDE)       // +4352
#define SMEM_FLOATS (OFF_CP + 16 * 34)               // +544 = 47136

// ---------------- reset barrier counters ------------------------------------
__global__ void reset_kernel() {
    if (threadIdx.x < BB) g_bar[threadIdx.x] = 0u;
}

// ---------------- embed gather + X-projection (runs once) ------------------
__global__ __launch_bounds__(128) void embed_proj_kernel(
    const int* __restrict__ idx, const float* __restrict__ emb,
    const float* __restrict__ Wg, const float* __restrict__ bg,
    const float* __restrict__ Wu, const float* __restrict__ bu)
{
    const int d0 = blockIdx.x * 32;
    const int m0 = blockIdx.y * 64;
    const int tid = threadIdx.x;
    __shared__ int   idxs[64];
    __shared__ float As[64][36];
    __shared__ float Ws[32][68];

    if (tid < 64) idxs[tid] = idx[m0 + tid];
    __syncthreads();

    const int tm = tid >> 4;
    const int tn = tid & 15;
    float acc[8][4];
#pragma unroll
    for (int i = 0; i < 8; i++)
#pragma unroll
        for (int j = 0; j < 4; j++) acc[i][j] = 0.f;

    for (int k0 = 0; k0 < DD; k0 += 32) {
#pragma unroll
        for (int i = 0; i < 4; i++) {
            int s = tid + i * 128; int n = s >> 3; int j4 = s & 7;
            float4 v = *(const float4*)(emb + (size_t)idxs[n] * DD + k0 + 4 * j4);
            *(float4*)&As[n][4 * j4] = v;
        }
#pragma unroll
        for (int i = 0; i < 2; i++) {
            int s = tid + i * 128; int kk = s >> 3; int j4 = s & 7;
            *(float4*)&Ws[kk][4 * j4]      = *(const float4*)(Wg + (size_t)(k0 + kk) * DD + d0 + 4 * j4);
            *(float4*)&Ws[kk][32 + 4 * j4] = *(const float4*)(Wu + (size_t)(k0 + kk) * DD + d0 + 4 * j4);
        }
        __syncthreads();
#pragma unroll
        for (int kk = 0; kk < 32; kk++) {
            float w[4]; *(float4*)w = *(float4*)&Ws[kk][4 * tn];
            float a[8];
#pragma unroll
            for (int i = 0; i < 8; i++) a[i] = As[tm + 8 * i][kk];
#pragma unroll
            for (int i = 0; i < 8; i++)
#pragma unroll
                for (int j = 0; j < 4; j++) acc[i][j] += a[i] * w[j];
        }
        __syncthreads();
    }

    if (tn < 8) {
#pragma unroll
        for (int i = 0; i < 8; i++) {
            int m = m0 + tm + 8 * i;
#pragma unroll
            for (int j = 0; j < 4; j++) {
                int c = d0 + 4 * tn + j;
                g_xg[(size_t)m * DD + c] = acc[i][j] + bg[c];
            }
        }
    } else {
#pragma unroll
        for (int i = 0; i < 8; i++) {
            int m = m0 + tm + 8 * i;
#pragma unroll
            for (int j = 0; j < 4; j++) {
                int c = d0 + 4 * (tn - 8) + j;
                g_xu[(size_t)m * DD + c] = acc[i][j] + bu[c];
            }
        }
    }
}

// ---------------- persistent recurrence kernel ------------------------------
// grid (16 dim-slices, 8 batches), 256 threads, ~188KB dyn SMEM, 1 CTA/SM.
// Weights live in SMEM across all 256 steps. Inner loop: node-paired FFMA2
// (1 LDS.128 A + 2 LDS.128 Wdup + 8 FFMA2 per kk per thread). Gating fully
// in registers. One 16-CTA global barrier per step per batch.
__global__ __launch_bounds__(256, 1) void persist_kernel(
    const float* __restrict__ Wg, const float* __restrict__ Wu,
    const float* __restrict__ nodes)
{
    extern __shared__ float sm[];
    float* Wsm = sm + OFF_WSM;     // [512][66] interleaved: [k][2j]=Wg, [2j+1]=Wu
    float* Wd  = sm + OFF_WDUP;    // [2][32][132] dup: [kk][4j..]=(g,g,u,u)
    float* Akb = sm + OFF_AK;      // [2][32][68] transposed H chunk [kk][n]
    float* cp  = sm + OFF_CP;      // [16][34] consensus partials

    const int d0 = blockIdx.x * 32;
    const int b  = blockIdx.y;
    const int tid = threadIdx.x;
    const int tm = tid >> 4;          // 0..15 -> nodes 4tm..4tm+3
    const int tn = tid & 15;          // 0..15 -> dims {tn, tn+16}

    // one-time: weight slice into SMEM, interleaved (g,u)
    for (int s = tid; s < 512 * 32; s += 256) {
        int k = s >> 5, j = s & 31;
        Wsm[k * W_STRIDE + 2 * j]     = Wg[(size_t)(DD + k) * DD + d0 + j];
        Wsm[k * W_STRIDE + 2 * j + 1] = Wu[(size_t)(DD + k) * DD + d0 + j];
    }
    // one-time: init H slice
    for (int s = tid; s < 64 * 8; s += 256) {
        int n = s >> 3, j4 = s & 7;
        *(float4*)(g_H[0] + ((size_t)b * NNODE + n) * DD + d0 + 4 * j4) =
            *(const float4*)(nodes + (size_t)n * DD + d0 + 4 * j4);
    }
    __syncthreads();
    __threadfence();
    if (tid == 0) {
        atomicAdd(&g_bar[b], 1u);
        while (((volatile unsigned*)g_bar)[b] < 16u) {}
        __threadfence();
    }
    __syncthreads();

    // staging ids: warp sw handles nodes 8sw..8sw+7; lane -> (node, k-quad)
    const int sw = tid >> 5;
    const int sl = tid & 31;
    const int sn = 8 * sw + (sl >> 2);
    const int sk = 4 * (sl & 3);
    // expansion ids
    const int ek = tid >> 3;          // kk 0..31
    const int eq = tid & 7;

    unsigned phase = 2;
    for (int t = 0; t < SS; t++, phase++) {
        const float* Hin  = g_H[t & 1]       + (size_t)b * NNODE * DD;
        float*       Hout = g_H[(t & 1) ^ 1] + (size_t)b * NNODE * DD;

        // epilogue operand prefetch (independent of GEMM)
        const int dA = d0 + tn, dB = d0 + tn + 16;
        const size_t xoff = ((size_t)b * SS + t) * DD;
        float xg1 = g_xg[xoff + dA], xg2 = g_xg[xoff + dB];
        float xu1 = g_xu[xoff + dA], xu2 = g_xu[xoff + dB];
        float hA[4], hB[4];
#pragma unroll
        for (int i = 0; i < 4; i++) {
            hA[i] = Hin[(size_t)(4 * tm + i) * DD + dA];
            hB[i] = Hin[(size_t)(4 * tm + i) * DD + dB];
        }

        // stage chunk 0 (A transposed) + expand Wdup chunk 0
        {
            float4 f0 = *(const float4*)(Hin + (size_t)sn * DD + sk);
            float4 f1 = *(const float4*)(Hin + (size_t)sn * DD + sk + 16);
            float* A0 = Akb;
            A0[(sk + 0) * AK_STRIDE + sn] = f0.x;
            A0[(sk + 1) * AK_STRIDE + sn] = f0.y;
            A0[(sk + 2) * AK_STRIDE + sn] = f0.z;
            A0[(sk + 3) * AK_STRIDE + sn] = f0.w;
            A0[(sk + 16) * AK_STRIDE + sn] = f1.x;
            A0[(sk + 17) * AK_STRIDE + sn] = f1.y;
            A0[(sk + 18) * AK_STRIDE + sn] = f1.z;
            A0[(sk + 19) * AK_STRIDE + sn] = f1.w;
            const float* src = Wsm + (size_t)ek * W_STRIDE;
            float* dst = Wd + (size_t)ek * WD_STRIDE;
#pragma unroll
            for (int r = 0; r < 4; r++) {
                int j = eq + 8 * r;
                float gv = src[2 * j], uv = src[2 * j + 1];
                *(float4*)&dst[4 * j] = make_float4(gv, gv, uv, uv);
            }
        }
        __syncthreads();

        u64 acc[2][4];
#pragma unroll
        for (int p = 0; p < 2; p++)
#pragma unroll
            for (int c = 0; c < 4; c++) acc[p][c] = 0ull;

        int buf = 0;
#pragma unroll 1
        for (int c = 0; c < 16; c++) {
            float4 p0, p1;
            if (c < 15) {
                p0 = *(const float4*)(Hin + (size_t)sn * DD + (c + 1) * 32 + sk);
                p1 = *(const float4*)(Hin + (size_t)sn * DD + (c + 1) * 32 + sk + 16);
            }
            const float* Ab = Akb + buf * (32 * AK_STRIDE);
            const float* Wb = Wd  + buf * (32 * WD_STRIDE);
#pragma unroll
            for (int kk = 0; kk < 32; kk++) {
                ulonglong2 av = *(const ulonglong2*)(Ab + kk * AK_STRIDE + 4 * tm);
                ulonglong2 w1 = *(const ulonglong2*)(Wb + kk * WD_STRIDE + 4 * tn);
                ulonglong2 w2 = *(const ulonglong2*)(Wb + kk * WD_STRIDE + 4 * (tn + 16));
                FFMA2(acc[0][0], av.x, w1.x); FFMA2(acc[0][1], av.x, w1.y);
                FFMA2(acc[0][2], av.x, w2.x); FFMA2(acc[0][3], av.x, w2.y);
                FFMA2(acc[1][0], av.y, w1.x); FFMA2(acc[1][1], av.y, w1.y);
                FFMA2(acc[1][2], av.y, w2.x); FFMA2(acc[1][3], av.y, w2.y);
            }
            if (c < 15) {
                float* An = Akb + (buf ^ 1) * (32 * AK_STRIDE);
                An[(sk + 0) * AK_STRIDE + sn] = p0.x;
                An[(sk + 1) * AK_STRIDE + sn] = p0.y;
                An[(sk + 2) * AK_STRIDE + sn] = p0.z;
                An[(sk + 3) * AK_STRIDE + sn] = p0.w;
                An[(sk + 16) * AK_STRIDE + sn] = p1.x;
                An[(sk + 17) * AK_STRIDE + sn] = p1.y;
                An[(sk + 18) * AK_STRIDE + sn] = p1.z;
                An[(sk + 19) * AK_STRIDE + sn] = p1.w;
                const float* src = Wsm + (size_t)((c + 1) * 32 + ek) * W_STRIDE;
                float* dst = Wd + (buf ^ 1) * (32 * WD_STRIDE) + (size_t)ek * WD_STRIDE;
#pragma unroll
                for (int r = 0; r < 4; r++) {
                    int j = eq + 8 * r;
                    float gv = src[2 * j], uv = src[2 * j + 1];
                    *(float4*)&dst[4 * j] = make_float4(gv, gv, uv, uv);
                }
            }
            __syncthreads();
            buf ^= 1;
        }

        // gating entirely in registers (thread owns matching g/u cols)
        float sA = 0.f, sB = 0.f;
#pragma unroll
        for (int p = 0; p < 2; p++) {
            float2 vg1 = u2f(acc[p][0]), vu1 = u2f(acc[p][1]);
            float2 vg2 = u2f(acc[p][2]), vu2 = u2f(acc[p][3]);
#pragma unroll
            for (int h = 0; h < 2; h++) {
                int n = 4 * tm + 2 * p + h;
                float gp1 = (h ? vg1.y : vg1.x) + xg1;
                float up1 = (h ? vu1.y : vu1.x) + xu1;
                float gp2 = (h ? vg2.y : vg2.x) + xg2;
                float up2 = (h ? vu2.y : vu2.x) + xu2;
                float s1 = __fdividef(1.f, 1.f + __expf(-gp1));
                float c1 = 1.f - __fdividef(2.f, 1.f + __expf(2.f * up1));
                float s2 = __fdividef(1.f, 1.f + __expf(-gp2));
                float c2 = 1.f - __fdividef(2.f, 1.f + __expf(2.f * up2));
                float h1 = hA[2 * p + h], h2 = hB[2 * p + h];
                float n1 = s1 * c1 + (1.f - s1) * h1;
                float n2 = s2 * c2 + (1.f - s2) * h2;
                Hout[(size_t)n * DD + dA] = n1;
                Hout[(size_t)n * DD + dB] = n2;
                sA += n1; sB += n2;
            }
        }
        cp[tm * 34 + tn]      = sA;
        cp[tm * 34 + tn + 16] = sB;
        __syncthreads();
        if (tid < 32) {
            float tot = 0.f;
#pragma unroll
            for (int g = 0; g < 16; g++) tot += cp[g * 34 + tid];
            g_cons[((size_t)b * SS + t) * DD + d0 + tid] = tot * (1.0f / 64.0f);
        }

        // inter-CTA barrier (per batch, 16 CTAs)
        __syncthreads();
        __threadfence();
        if (tid == 0) {
            atomicAdd(&g_bar[b], 1u);
            unsigned tgt = 16u * phase;
            while (((volatile unsigned*)g_bar)[b] < tgt) {}
            __threadfence();
        }
        __syncthreads();
    }
}

// ---------------- layernorm over consensus rows -----------------------------
__global__ void layernorm_kernel(const float* __restrict__ lnw,
                                 const float* __restrict__ lnb)
{
    const int r = blockIdx.x;
    const int tid = threadIdx.x;
    const float* x = g_cons + (size_t)r * DD;
    float x0 = x[tid], x1 = x[tid + 256];
    __shared__ float red[256];
    red[tid] = x0 + x1;
    __syncthreads();
    for (int s = 128; s > 0; s >>= 1) {
        if (tid < s) red[tid] += red[tid + s];
        __syncthreads();
    }
    float mu = red[0] * (1.f / 512.f);
    __syncthreads();
    float dv0 = x0 - mu, dv1 = x1 - mu;
    red[tid] = dv0 * dv0 + dv1 * dv1;
    __syncthreads();
    for (int s = 128; s > 0; s >>= 1) {
        if (tid < s) red[tid] += red[tid + s];
        __syncthreads();
    }
    float var = red[0] * (1.f / 512.f);
    float rs = rsqrtf(var + 1e-5f);
    g_cln[(size_t)r * DD + tid]       = dv0 * rs * lnw[tid] + lnb[tid];
    g_cln[(size_t)r * DD + tid + 256] = dv1 * rs * lnw[tid + 256] + lnb[tid + 256];
}

// ---------------- logits GEMM: [2048,512] @ [512,32000] + bh (FFMA2) --------
__global__ __launch_bounds__(128) void logits_kernel(
    const float* __restrict__ Wh, const float* __restrict__ bh,
    float* __restrict__ out)
{
    const int v0 = blockIdx.x * 64;
    const int m0 = blockIdx.y * 64;
    const int tid = threadIdx.x;
    __shared__ float As2[32 * 138];   // [kk][2m dup]
    __shared__ float Bs[32 * 68];     // [kk][v]
    const int tm = tid >> 4;
    const int tn = tid & 15;
    u64 acc[8][2];
#pragma unroll
    for (int i = 0; i < 8; i++) { acc[i][0] = 0ull; acc[i][1] = 0ull; }

    float4 pa[4], pb[4];
#pragma unroll
    for (int i = 0; i < 4; i++) {
        int s = tid + i * 128; int n = s >> 3; int j4 = s & 7;
        pa[i] = *(const float4*)(g_cln + (size_t)(m0 + n) * DD + 4 * j4);
    }
#pragma unroll
    for (int i = 0; i < 4; i++) {
        int s = tid + i * 128; int kk = s >> 4; int j4 = s & 15;
        pb[i] = *(const float4*)(Wh + (size_t)kk * VV + v0 + 4 * j4);
    }

    for (int k0 = 0; k0 < DD; k0 += 32) {
#pragma unroll
        for (int i = 0; i < 4; i++) {
            int s = tid + i * 128; int n = s >> 3; int j4 = s & 7;
            *(float2*)&As2[(4 * j4 + 0) * 138 + 2 * n] = make_float2(pa[i].x, pa[i].x);
            *(float2*)&As2[(4 * j4 + 1) * 138 + 2 * n] = make_float2(pa[i].y, pa[i].y);
            *(float2*)&As2[(4 * j4 + 2) * 138 + 2 * n] = make_float2(pa[i].z, pa[i].z);
            *(float2*)&As2[(4 * j4 + 3) * 138 + 2 * n] = make_float2(pa[i].w, pa[i].w);
        }
#pragma unroll
        for (int i = 0; i < 4; i++) {
            int s = tid + i * 128; int kk = s >> 4; int j4 = s & 15;
            *(float4*)&Bs[kk * 68 + 4 * j4] = pb[i];
        }
        __syncthreads();

        const int k1 = k0 + 32;
        if (k1 < DD) {
#pragma unroll
            for (int i = 0; i < 4; i++) {
                int s = tid + i * 128; int n = s >> 3; int j4 = s & 7;
                pa[i] = *(const float4*)(g_cln + (size_t)(m0 + n) * DD + k1 + 4 * j4);
            }
#pragma unroll
            for (int i = 0; i < 4; i++) {
                int s = tid + i * 128; int kk = s >> 4; int j4 = s & 15;
                pb[i] = *(const float4*)(Wh + (size_t)(k1 + kk) * VV + v0 + 4 * j4);
            }
        }

#pragma unroll
        for (int kk = 0; kk < 32; kk++) {
            const u64* wp = (const u64*)(Bs + kk * 68 + 4 * tn);
            u64 w0 = wp[0], w1 = wp[1];
            const float* ar = As2 + kk * 138 + 2 * tm;
#pragma unroll
            for (int i = 0; i < 8; i++) {
                u64 a = *(const u64*)(ar + 16 * i);
                FFMA2(acc[i][0], a, w0);
                FFMA2(acc[i][1], a, w1);
            }
        }
        __syncthreads();
    }

    float4 bias = *(const float4*)(bh + v0 + 4 * tn);
#pragma unroll
    for (int i = 0; i < 8; i++) {
        float2 p0 = u2f(acc[i][0]), p1 = u2f(acc[i][1]);
        float4 o = make_float4(p0.x + bias.x, p0.y + bias.y, p1.x + bias.z, p1.y + bias.w);
        *(float4*)(out + (size_t)(m0 + tm + 8 * i) * VV + v0 + 4 * tn) = o;
    }
}

// ---------------- launch ----------------------------------------------------
extern "C" void kernel_launch(void* const* d_in, const int* in_sizes, int n_in,
                              void* d_out, int out_size) {
    (void)in_sizes; (void)n_in; (void)out_size;
    const int*   idx   = (const int*)  d_in[0];
    const float* emb   = (const float*)d_in[1];
    const float* nodes = (const float*)d_in[2];
    const float* Wg    = (const float*)d_in[3];
    const float* bg    = (const float*)d_in[4];
    const float* Wu    = (const float*)d_in[5];
    const float* bu    = (const float*)d_in[6];
    const float* lnw   = (const float*)d_in[7];
    const float* lnb   = (const float*)d_in[8];
    const float* Wh    = (const float*)d_in[9];
    const float* bh    = (const float*)d_in[10];
    float* out = (float*)d_out;

    const int smem_bytes = SMEM_FLOATS * 4;  // 188,544
    cudaFuncSetAttribute(persist_kernel,
                         cudaFuncAttributeMaxDynamicSharedMemorySize, smem_bytes);

    reset_kernel<<<1, 32>>>();
    embed_proj_kernel<<<dim3(16, 32), 128>>>(idx, emb, Wg, bg, Wu, bu);
    persist_kernel<<<dim3(16, 8), 256, smem_bytes>>>(Wg, Wu, nodes);
    layernorm_kernel<<<BB * SS, 256>>>(lnw, lnb);
    logits_kernel<<<dim3(VV / 64, (BB * SS) / 64), 128>>>(Wh, bh, out);
}